// round 16
// baseline (speedup 1.0000x reference)
#include <cuda_runtime.h>
#include <cuda_bf16.h>
#include <cstdint>

#define NN 4096
#define FF 512
#define DD 128
#define HH 8
#define KC 64
#define NCHUNK (NN / KC)

// ---------------- scratch (static device globals; no allocs) ----------------
__device__ __nv_bfloat16 g_featb[NN * FF];          // 4 MB
__device__ __nv_bfloat16 g_Wb[HH * FF * DD];        // 1 MB
__device__ __nv_bfloat16 g_Whb[HH * NN * DD];       // 8 MB row-major [h][j][d]
__device__ float g_ratio[HH * NN];                  // exp(-0.8 s1)
__device__ float g_e2p[HH * NN];                    // exp(s2)
__device__ float g_e2n[HH * NN];                    // exp(0.2 s2)
__device__ unsigned g_adjbits[NN * (NN / 32)];      // 2 MB
__device__ float g_haccum[HH * NN * DD];            // 16 MB per-head elu(h')

// ---------------- helpers ----------------
__device__ __forceinline__ unsigned pack_bf16x2(float lo, float hi) {
    unsigned r;
    asm("cvt.rn.bf16x2.f32 %0, %1, %2;" : "=r"(r) : "f"(hi), "f"(lo));
    return r;
}
__device__ __forceinline__ unsigned smem_u32(const void* p) {
    return (unsigned)__cvta_generic_to_shared(p);
}
__device__ __forceinline__ unsigned SWZ(unsigned off) {        // SW128 swizzle
    return off ^ ((off >> 3) & 0x70);
}
__device__ __forceinline__ void ldsm_x4(unsigned addr, unsigned& r0, unsigned& r1,
                                        unsigned& r2, unsigned& r3) {
    asm volatile("ldmatrix.sync.aligned.m8n8.x4.shared.b16 {%0,%1,%2,%3}, [%4];"
                 : "=r"(r0), "=r"(r1), "=r"(r2), "=r"(r3) : "r"(addr));
}
__device__ __forceinline__ void ldsm_x4_t(unsigned addr, unsigned& r0, unsigned& r1,
                                          unsigned& r2, unsigned& r3) {
    asm volatile("ldmatrix.sync.aligned.m8n8.x4.trans.shared.b16 {%0,%1,%2,%3}, [%4];"
                 : "=r"(r0), "=r"(r1), "=r"(r2), "=r"(r3) : "r"(addr));
}
__device__ __forceinline__ void mma_bf16(float* c, unsigned a0, unsigned a1, unsigned a2,
                                         unsigned a3, unsigned b0, unsigned b1) {
    asm volatile(
        "mma.sync.aligned.m16n8k16.row.col.f32.bf16.bf16.f32 "
        "{%0,%1,%2,%3}, {%4,%5,%6,%7}, {%8,%9}, {%0,%1,%2,%3};"
        : "+f"(c[0]), "+f"(c[1]), "+f"(c[2]), "+f"(c[3])
        : "r"(a0), "r"(a1), "r"(a2), "r"(a3), "r"(b0), "r"(b1));
}
#define CP_ASYNC16(dst, src) \
    asm volatile("cp.async.cg.shared.global [%0], [%1], 16;" :: "r"(dst), "l"(src))
#define CP_COMMIT asm volatile("cp.async.commit_group;")
#define CP_WAIT1 asm volatile("cp.async.wait_group 1;")
#define CP_WAIT0 asm volatile("cp.async.wait_group 0;")

__device__ __forceinline__ void sts128(unsigned addr, unsigned a, unsigned b,
                                       unsigned c, unsigned d) {
    asm volatile("st.shared.v4.b32 [%0], {%1,%2,%3,%4};"
                 :: "r"(addr), "r"(a), "r"(b), "r"(c), "r"(d));
}
__device__ __forceinline__ void lds128f(float4& v, unsigned addr) {
    asm volatile("ld.shared.v4.f32 {%0,%1,%2,%3}, [%4];"
                 : "=f"(v.x), "=f"(v.y), "=f"(v.z), "=f"(v.w) : "r"(addr));
}
__device__ __forceinline__ float elu1(float v) {
    return (v > 0.0f) ? v : (__expf(v) - 1.0f);
}

// ---------------- kernel 1: convert feature/W to bf16 ----------------
__global__ void prep_kernel(const float* __restrict__ feature, const float* __restrict__ W) {
    int i = blockIdx.x * 256 + threadIdx.x;          // 2048 blocks -> 524288 threads
    #pragma unroll
    for (int r = 0; r < 4; r++) {
        int k = i + r * 524288;                       // NN*FF
        g_featb[k] = __float2bfloat16(feature[k]);
    }
    g_Wb[i] = __float2bfloat16(W[i]);                // HH*FF*DD
}

// ---------------- kernel 2: adjacency -> bitmask ----------------
__global__ void pack_adj_kernel(const int* __restrict__ adj) {
    int gid = blockIdx.x * 256 + threadIdx.x;        // 65536 blocks
    int w = gid >> 5;
    int lane = gid & 31;
    unsigned mask = __ballot_sync(0xffffffffu, adj[(size_t)w * 32 + lane] > 0);
    if (lane == 0) g_adjbits[w] = mask;
}

// ---------------- kernel 3: Wh = feature @ W[h]; cp.async pipelined ----------------
// Epilogue emits Wh (row-major) + ratio/e2p/e2n tables for the attn kernel.
#define PSA_BUF 18432          // 128 * 144
#define PSB_BUF 17408          // 64 * 272
#define POFF_B  (2 * PSA_BUF)  // 36864
#define PROJ_SMEM_BYTES (POFF_B + 2 * PSB_BUF + 256)   // ~72 KB

__global__ void __launch_bounds__(256, 2) proj_kernel(const float* __restrict__ a1,
                                                      const float* __restrict__ a2) {
    extern __shared__ char psm[];
    unsigned sbase = (smem_u32(psm) + 127u) & ~127u;
    unsigned sA0 = sbase;                 // 2 x 18432
    unsigned sB0 = sbase + POFF_B;        // 2 x 17408
    __shared__ float sA1[128], sA2[128];

    int h = blockIdx.y;
    int rowbase = blockIdx.x * 128;
    int t = threadIdx.x;
    int warp = t >> 5, lane = t & 31;
    int g = lane >> 2, tid4 = lane & 3;
    int m0 = warp * 16;
    int lr = (lane & 7) + ((lane & 8) ? 8 : 0);
    int lc = (lane & 16) ? 8 : 0;

    if (t < 128) sA1[t] = a1[h * DD + t];
    else sA2[t - 128] = a2[h * DD + (t - 128)];

    float acc[16][4];
    #pragma unroll
    for (int i = 0; i < 16; i++)
        #pragma unroll
        for (int j = 0; j < 4; j++) acc[i][j] = 0.0f;

    // issue chunk 0
    {
        #pragma unroll
        for (int r = 0; r < 4; r++) {
            int li = r * 256 + t;
            int row = li >> 3, q = li & 7;
            CP_ASYNC16(sA0 + row * 144 + q * 16,
                       g_featb + (size_t)(rowbase + row) * FF + q * 8);
        }
        #pragma unroll
        for (int r = 0; r < 4; r++) {
            int li = r * 256 + t;
            int row = li >> 4, q = li & 15;
            CP_ASYNC16(sB0 + row * 272 + q * 16,
                       g_Wb + ((size_t)h * FF + row) * DD + q * 8);
        }
    }
    CP_COMMIT;

    for (int c = 0; c < FF / 64; c++) {
        int kc = c * 64;
        if (c + 1 < FF / 64) {
            int nb_ = (c + 1) & 1;
            #pragma unroll
            for (int r = 0; r < 4; r++) {
                int li = r * 256 + t;
                int row = li >> 3, q = li & 7;
                CP_ASYNC16(sA0 + nb_ * PSA_BUF + row * 144 + q * 16,
                           g_featb + (size_t)(rowbase + row) * FF + kc + 64 + q * 8);
            }
            #pragma unroll
            for (int r = 0; r < 4; r++) {
                int li = r * 256 + t;
                int row = li >> 4, q = li & 15;
                CP_ASYNC16(sB0 + nb_ * PSB_BUF + row * 272 + q * 16,
                           g_Wb + ((size_t)h * FF + kc + 64 + row) * DD + q * 8);
            }
        }
        CP_COMMIT;
        if (c + 1 < FF / 64) { CP_WAIT1; } else { CP_WAIT0; }
        __syncthreads();

        int buf = c & 1;
        unsigned aBase = sA0 + buf * PSA_BUF;
        unsigned bBase = sB0 + buf * PSB_BUF;
        #pragma unroll
        for (int kk = 0; kk < 64; kk += 16) {
            unsigned a0, a1r, a2r, a3;
            ldsm_x4(aBase + (m0 + lr) * 144 + (kk + lc) * 2, a0, a1r, a2r, a3);
            #pragma unroll
            for (int nb = 0; nb < 8; nb++) {
                unsigned b0, b1, b2, b3;
                ldsm_x4_t(bBase + (kk + lr) * 272 + (nb * 16 + lc) * 2, b0, b1, b2, b3);
                mma_bf16(acc[2 * nb], a0, a1r, a2r, a3, b0, b1);
                mma_bf16(acc[2 * nb + 1], a0, a1r, a2r, a3, b2, b3);
            }
        }
        __syncthreads();
    }

    int row_lo = rowbase + m0 + g;
    int row_hi = row_lo + 8;

    // write Wh (bf16, row-major [h][j][d])
    __nv_bfloat16* outlo = g_Whb + ((size_t)h * NN + row_lo) * DD;
    __nv_bfloat16* outhi = g_Whb + ((size_t)h * NN + row_hi) * DD;
    #pragma unroll
    for (int i = 0; i < 16; i++) {
        int col = i * 8 + 2 * tid4;
        *(unsigned*)(outlo + col) = pack_bf16x2(acc[i][0], acc[i][1]);
        *(unsigned*)(outhi + col) = pack_bf16x2(acc[i][2], acc[i][3]);
    }

    // fused s1/s2 dot products from fp32 accumulators
    float d1lo = 0, d2lo = 0, d1hi = 0, d2hi = 0;
    #pragma unroll
    for (int i = 0; i < 16; i++) {
        int col = i * 8 + 2 * tid4;
        float v1a = sA1[col], v1b = sA1[col + 1];
        float v2a = sA2[col], v2b = sA2[col + 1];
        d1lo += acc[i][0] * v1a + acc[i][1] * v1b;
        d1hi += acc[i][2] * v1a + acc[i][3] * v1b;
        d2lo += acc[i][0] * v2a + acc[i][1] * v2b;
        d2hi += acc[i][2] * v2a + acc[i][3] * v2b;
    }
    #pragma unroll
    for (int o = 1; o <= 2; o <<= 1) {
        d1lo += __shfl_xor_sync(0xffffffffu, d1lo, o);
        d1hi += __shfl_xor_sync(0xffffffffu, d1hi, o);
        d2lo += __shfl_xor_sync(0xffffffffu, d2lo, o);
        d2hi += __shfl_xor_sync(0xffffffffu, d2hi, o);
    }
    if (tid4 == 0) {
        int ilo = h * NN + row_lo, ihi = h * NN + row_hi;
        g_ratio[ilo] = __expf(-0.8f * d1lo); g_ratio[ihi] = __expf(-0.8f * d1hi);
        g_e2p[ilo] = __expf(d2lo);           g_e2p[ihi] = __expf(d2hi);
        g_e2n[ilo] = __expf(0.2f * d2lo);    g_e2n[ihi] = __expf(0.2f * d2hi);
    }
}

// ---------------- kernel 4: fused masked-softmax aggregation ----------------
// EXACT structure that measured 145.9us: q_ij = mask*max(e2p_j, ratio_i*e2n_j),
// single P buffer + double B, ones-mma Z, per-head g_haccum stores.
#define OFF_P    0
#define OFF_B    16384
#define OFF_E2P  49152
#define OFF_E2N  65536
#define ATTN_SMEM_BYTES (81920 + 1024)

__global__ void __launch_bounds__(256, 2) attn_kernel() {
    extern __shared__ char smraw[];
    unsigned sb = (smem_u32(smraw) + 1023u) & ~1023u;
    unsigned sP = sb + OFF_P;
    unsigned sBb = sb + OFF_B;                 // + buf*16384 + half*8192
    unsigned sE2P = sb + OFF_E2P, sE2N = sb + OFF_E2N;

    int t = threadIdx.x;
    int w = t >> 5, lane = t & 31;
    int g = lane >> 2, tid4 = lane & 3;
    int mw = w & 3, nw = w >> 2;
    int m0 = mw * 32;
    int n0 = nw * 64;
    int lr = (lane & 7) + ((lane & 8) ? 8 : 0);
    int lc = (lane & 16) ? 8 : 0;
    int h = blockIdx.y;
    int rowbase = blockIdx.x * 128;

    // score-gen mapping: thread -> (row, 32-col half)
    int prow = t >> 1;
    int phalf = t & 1;
    int srow = rowbase + prow;
    float ratio = g_ratio[h * NN + srow];

    // stage e2p/e2n (whole head, 16 KB each) + B tile 0, one cp.async group
    #pragma unroll
    for (int r = 0; r < 4; r++) {
        CP_ASYNC16(sE2P + (t + r * 256) * 16, g_e2p + (size_t)h * NN + (t + r * 256) * 4);
        CP_ASYNC16(sE2N + (t + r * 256) * 16, g_e2n + (size_t)h * NN + (t + r * 256) * 4);
    }
    {
        const __nv_bfloat16* src = g_Whb + (size_t)h * NN * DD;
        #pragma unroll
        for (int r = 0; r < 4; r++) {
            int li = r * 256 + t;
            int row = li >> 4, q = li & 15;
            CP_ASYNC16(sBb + (q >> 3) * 8192 + SWZ(row * 128 + (q & 7) * 16),
                       src + row * DD + q * 8);
        }
    }
    CP_COMMIT;
    CP_WAIT0;
    __syncthreads();

    float acc[16][4];
    #pragma unroll
    for (int i = 0; i < 16; i++)
        #pragma unroll
        for (int j = 0; j < 4; j++) acc[i][j] = 0.0f;
    float zA[4] = {0, 0, 0, 0}, zB[4] = {0, 0, 0, 0};
    const unsigned ONES = 0x3f803f80u;          // bf16 (1.0, 1.0)

    for (int i = 0; i < NCHUNK; i++) {
        int kc = i * KC;
        // prefetch B(i+1)
        if (i + 1 < NCHUNK) {
            const __nv_bfloat16* src = g_Whb + ((size_t)h * NN + kc + KC) * DD;
            unsigned dstb = sBb + ((i + 1) & 1) * 16384;
            #pragma unroll
            for (int r = 0; r < 4; r++) {
                int li = r * 256 + t;
                int row = li >> 4, q = li & 15;
                CP_ASYNC16(dstb + (q >> 3) * 8192 + SWZ(row * 128 + (q & 7) * 16),
                           src + row * DD + q * 8);
            }
        }
        CP_COMMIT;

        // score-gen: 32 q values for (srow, cols kc+phalf*32 .. +31) -> swizzled sP
        unsigned bw = g_adjbits[(size_t)srow * (NN / 32) + i * 2 + phalf];
        #pragma unroll
        for (int gi = 0; gi < 4; gi++) {
            int c = phalf * 32 + gi * 8;
            float4 ep0, ep1, en0, en1;
            lds128f(ep0, sE2P + (kc + c) * 4);
            lds128f(ep1, sE2P + (kc + c) * 4 + 16);
            lds128f(en0, sE2N + (kc + c) * 4);
            lds128f(en1, sE2N + (kc + c) * 4 + 16);
            unsigned mb = bw >> (gi * 8);
            float q0 = (mb & 1u)   ? fmaxf(ep0.x, ratio * en0.x) : 0.0f;
            float q1 = (mb & 2u)   ? fmaxf(ep0.y, ratio * en0.y) : 0.0f;
            float q2 = (mb & 4u)   ? fmaxf(ep0.z, ratio * en0.z) : 0.0f;
            float q3 = (mb & 8u)   ? fmaxf(ep0.w, ratio * en0.w) : 0.0f;
            float q4 = (mb & 16u)  ? fmaxf(ep1.x, ratio * en1.x) : 0.0f;
            float q5 = (mb & 32u)  ? fmaxf(ep1.y, ratio * en1.y) : 0.0f;
            float q6 = (mb & 64u)  ? fmaxf(ep1.z, ratio * en1.z) : 0.0f;
            float q7 = (mb & 128u) ? fmaxf(ep1.w, ratio * en1.w) : 0.0f;
            sts128(sP + SWZ(prow * 128 + c * 2),
                   pack_bf16x2(q0, q1), pack_bf16x2(q2, q3),
                   pack_bf16x2(q4, q5), pack_bf16x2(q6, q7));
        }

        CP_WAIT1;                 // B(i) resident; B(i+1) may be in flight
        __syncthreads();          // P(i) visible to all warps

        unsigned bhalf = sBb + (i & 1) * 16384 + nw * 8192;
        #pragma unroll
        for (int kk = 0; kk < 4; kk++) {
            unsigned A00, A01, A02, A03, A10, A11, A12, A13;
            ldsm_x4(sP + SWZ((m0 + lr) * 128 + (kk * 16 + lc) * 2), A00, A01, A02, A03);
            ldsm_x4(sP + SWZ((m0 + 16 + lr) * 128 + (kk * 16 + lc) * 2), A10, A11, A12, A13);
            #pragma unroll
            for (int nb4 = 0; nb4 < 4; nb4++) {
                unsigned b0, b1, b2, b3;
                ldsm_x4_t(bhalf + SWZ((kk * 16 + lr) * 128 + (nb4 * 16 + lc) * 2),
                          b0, b1, b2, b3);
                mma_bf16(acc[2 * nb4],     A00, A01, A02, A03, b0, b1);
                mma_bf16(acc[2 * nb4 + 1], A00, A01, A02, A03, b2, b3);
                mma_bf16(acc[8 + 2 * nb4],     A10, A11, A12, A13, b0, b1);
                mma_bf16(acc[8 + 2 * nb4 + 1], A10, A11, A12, A13, b2, b3);
            }
            mma_bf16(zA, A00, A01, A02, A03, ONES, ONES);   // Z rows m0+g, m0+g+8
            mma_bf16(zB, A10, A11, A12, A13, ONES, ONES);   // Z rows +16, +24
        }
        __syncthreads();          // P(i) consumed; safe to overwrite next iter
    }

    // normalize + ELU + per-head store
    int r0 = rowbase + m0 + g;
    float i0 = 1.0f / zA[0];
    float i1 = 1.0f / zA[2];
    float i2 = 1.0f / zB[0];
    float i3 = 1.0f / zB[2];
    float* o0 = g_haccum + ((size_t)h * NN + r0) * DD;
    float* o1 = o0 + 8 * DD;
    float* o2 = o0 + 16 * DD;
    float* o3 = o0 + 24 * DD;
    #pragma unroll
    for (int nb = 0; nb < 8; nb++) {
        int col = n0 + nb * 8 + 2 * tid4;
        float2 v0 = make_float2(elu1(acc[nb][0] * i0), elu1(acc[nb][1] * i0));
        float2 v1 = make_float2(elu1(acc[nb][2] * i1), elu1(acc[nb][3] * i1));
        float2 v2 = make_float2(elu1(acc[8 + nb][0] * i2), elu1(acc[8 + nb][1] * i2));
        float2 v3 = make_float2(elu1(acc[8 + nb][2] * i3), elu1(acc[8 + nb][3] * i3));
        *(float2*)(o0 + col) = v0;
        *(float2*)(o1 + col) = v1;
        *(float2*)(o2 + col) = v2;
        *(float2*)(o3 + col) = v3;
    }
}

// ---------------- kernel 5: head-sum -> /H -> log_softmax -> mean ----------------
__global__ void final_kernel(float* __restrict__ out) {
    int warp = threadIdx.x >> 5;
    int lane = threadIdx.x & 31;
    int row = blockIdx.x * 8 + warp;               // 512 blocks -> 4096 rows
    float x0 = 0, x1 = 0, x2 = 0, x3 = 0;
    #pragma unroll
    for (int hh = 0; hh < HH; hh++) {
        float4 v = *(const float4*)(g_haccum + ((size_t)hh * NN + row) * DD + lane * 4);
        x0 += v.x; x1 += v.y; x2 += v.z; x3 += v.w;
    }
    x0 *= 0.125f; x1 *= 0.125f; x2 *= 0.125f; x3 *= 0.125f;
    float mx = fmaxf(fmaxf(x0, x1), fmaxf(x2, x3));
    #pragma unroll
    for (int o = 16; o; o >>= 1) mx = fmaxf(mx, __shfl_xor_sync(0xffffffffu, mx, o));
    float se = __expf(x0 - mx) + __expf(x1 - mx) + __expf(x2 - mx) + __expf(x3 - mx);
    float sx = x0 + x1 + x2 + x3;
    #pragma unroll
    for (int o = 16; o; o >>= 1) {
        se += __shfl_xor_sync(0xffffffffu, se, o);
        sx += __shfl_xor_sync(0xffffffffu, sx, o);
    }
    if (lane == 0) out[row] = sx * (1.0f / 128.0f) - mx - logf(se);
}

// ---------------- launch (fork-join: pack_adj overlaps prep+proj; alloc-safe) ----------------
extern "C" void kernel_launch(void* const* d_in, const int* in_sizes, int n_in,
                              void* d_out, int out_size) {
    const float* feature = (const float*)d_in[0];
    const int* adj = (const int*)d_in[1];
    const float* W = (const float*)d_in[2];
    const float* a1 = (const float*)d_in[3];
    const float* a2 = (const float*)d_in[4];
    float* out = (float*)d_out;

    static cudaStream_t s_pack = nullptr;
    static cudaEvent_t ev_fork = nullptr, ev_join = nullptr;
    if (!s_pack) {   // created on the (uncaptured) correctness call; 1 stream passed twice
        cudaStreamCreateWithFlags(&s_pack, cudaStreamNonBlocking);
        cudaEventCreateWithFlags(&ev_fork, cudaEventDisableTiming);
        cudaEventCreateWithFlags(&ev_join, cudaEventDisableTiming);
        cudaFuncSetAttribute(proj_kernel, cudaFuncAttributeMaxDynamicSharedMemorySize,
                             PROJ_SMEM_BYTES);
        cudaFuncSetAttribute(attn_kernel, cudaFuncAttributeMaxDynamicSharedMemorySize,
                             ATTN_SMEM_BYTES);
    }

    // fork: pack_adj (HBM-bound, independent) runs concurrently with prep+proj
    cudaEventRecord(ev_fork, 0);
    cudaStreamWaitEvent(s_pack, ev_fork, 0);
    pack_adj_kernel<<<65536, 256, 0, s_pack>>>(adj);
    cudaEventRecord(ev_join, s_pack);

    prep_kernel<<<2048, 256>>>(feature, W);
    proj_kernel<<<dim3(32, 8), 256, PROJ_SMEM_BYTES>>>(a1, a2);

    // join: attn needs g_adjbits
    cudaStreamWaitEvent(0, ev_join, 0);
    attn_kernel<<<dim3(32, 8), 256, ATTN_SMEM_BYTES>>>();
    final_kernel<<<512, 256>>>(out);
}

// round 17
// speedup vs baseline: 1.0074x; 1.0074x over previous
#include <cuda_runtime.h>
#include <cuda_bf16.h>
#include <cstdint>

#define NN 4096
#define FF 512
#define DD 128
#define HH 8
#define KC 64
#define NCHUNK (NN / KC)

// ---------------- scratch (static device globals; no allocs) ----------------
__device__ __nv_bfloat16 g_featb[NN * FF];          // 4 MB
__device__ __nv_bfloat16 g_Wb[HH * FF * DD];        // 1 MB
__device__ __nv_bfloat16 g_Whb[HH * NN * DD];       // 8 MB row-major [h][j][d]
__device__ float g_ratio[HH * NN];                  // exp(-0.8 s1)
__device__ float g_e2p[HH * NN];                    // exp(s2)
__device__ float g_e2n[HH * NN];                    // exp(0.2 s2)
__device__ unsigned g_adjbits[NN * (NN / 32)];      // 2 MB
__device__ float g_haccum[HH * NN * DD];            // 16 MB per-head elu(h')

// ---------------- helpers ----------------
__device__ __forceinline__ unsigned pack_bf16x2(float lo, float hi) {
    unsigned r;
    asm("cvt.rn.bf16x2.f32 %0, %1, %2;" : "=r"(r) : "f"(hi), "f"(lo));
    return r;
}
__device__ __forceinline__ unsigned smem_u32(const void* p) {
    return (unsigned)__cvta_generic_to_shared(p);
}
__device__ __forceinline__ unsigned SWZ(unsigned off) {        // SW128 swizzle
    return off ^ ((off >> 3) & 0x70);
}
__device__ __forceinline__ void ldsm_x4(unsigned addr, unsigned& r0, unsigned& r1,
                                        unsigned& r2, unsigned& r3) {
    asm volatile("ldmatrix.sync.aligned.m8n8.x4.shared.b16 {%0,%1,%2,%3}, [%4];"
                 : "=r"(r0), "=r"(r1), "=r"(r2), "=r"(r3) : "r"(addr));
}
__device__ __forceinline__ void ldsm_x4_t(unsigned addr, unsigned& r0, unsigned& r1,
                                          unsigned& r2, unsigned& r3) {
    asm volatile("ldmatrix.sync.aligned.m8n8.x4.trans.shared.b16 {%0,%1,%2,%3}, [%4];"
                 : "=r"(r0), "=r"(r1), "=r"(r2), "=r"(r3) : "r"(addr));
}
__device__ __forceinline__ void mma_bf16(float* c, unsigned a0, unsigned a1, unsigned a2,
                                         unsigned a3, unsigned b0, unsigned b1) {
    asm volatile(
        "mma.sync.aligned.m16n8k16.row.col.f32.bf16.bf16.f32 "
        "{%0,%1,%2,%3}, {%4,%5,%6,%7}, {%8,%9}, {%0,%1,%2,%3};"
        : "+f"(c[0]), "+f"(c[1]), "+f"(c[2]), "+f"(c[3])
        : "r"(a0), "r"(a1), "r"(a2), "r"(a3), "r"(b0), "r"(b1));
}
#define CP_ASYNC16(dst, src) \
    asm volatile("cp.async.cg.shared.global [%0], [%1], 16;" :: "r"(dst), "l"(src))
#define CP_COMMIT asm volatile("cp.async.commit_group;")
#define CP_WAIT1 asm volatile("cp.async.wait_group 1;")
#define CP_WAIT0 asm volatile("cp.async.wait_group 0;")

__device__ __forceinline__ void sts128(unsigned addr, unsigned a, unsigned b,
                                       unsigned c, unsigned d) {
    asm volatile("st.shared.v4.b32 [%0], {%1,%2,%3,%4};"
                 :: "r"(addr), "r"(a), "r"(b), "r"(c), "r"(d));
}
__device__ __forceinline__ void lds128f(float4& v, unsigned addr) {
    asm volatile("ld.shared.v4.f32 {%0,%1,%2,%3}, [%4];"
                 : "=f"(v.x), "=f"(v.y), "=f"(v.z), "=f"(v.w) : "r"(addr));
}
__device__ __forceinline__ float elu1(float v) {
    return (v > 0.0f) ? v : (__expf(v) - 1.0f);
}

// ---------------- kernel 1: convert feature/W to bf16 ----------------
__global__ void prep_kernel(const float* __restrict__ feature, const float* __restrict__ W) {
    int i = blockIdx.x * 256 + threadIdx.x;          // 2048 blocks -> 524288 threads
    #pragma unroll
    for (int r = 0; r < 4; r++) {
        int k = i + r * 524288;                       // NN*FF
        g_featb[k] = __float2bfloat16(feature[k]);
    }
    g_Wb[i] = __float2bfloat16(W[i]);                // HH*FF*DD
}

// ---------------- kernel 2: adjacency -> bitmask ----------------
__global__ void pack_adj_kernel(const int* __restrict__ adj) {
    int gid = blockIdx.x * 256 + threadIdx.x;        // 65536 blocks
    int w = gid >> 5;
    int lane = gid & 31;
    unsigned mask = __ballot_sync(0xffffffffu, adj[(size_t)w * 32 + lane] > 0);
    if (lane == 0) g_adjbits[w] = mask;
}

// ---------------- kernel 3: Wh = feature @ W[h]; cp.async pipelined; PDL consumer ----------------
#define PSA_BUF 18432          // 128 * 144
#define PSB_BUF 17408          // 64 * 272
#define POFF_B  (2 * PSA_BUF)  // 36864
#define PROJ_SMEM_BYTES (POFF_B + 2 * PSB_BUF + 256)   // ~72 KB

__global__ void __launch_bounds__(256, 2) proj_kernel(const float* __restrict__ a1,
                                                      const float* __restrict__ a2) {
    extern __shared__ char psm[];
    unsigned sbase = (smem_u32(psm) + 127u) & ~127u;
    unsigned sA0 = sbase;                 // 2 x 18432
    unsigned sB0 = sbase + POFF_B;        // 2 x 17408
    __shared__ float sA1[128], sA2[128];

    int h = blockIdx.y;
    int rowbase = blockIdx.x * 128;
    int t = threadIdx.x;
    int warp = t >> 5, lane = t & 31;
    int g = lane >> 2, tid4 = lane & 3;
    int m0 = warp * 16;
    int lr = (lane & 7) + ((lane & 8) ? 8 : 0);
    int lc = (lane & 16) ? 8 : 0;

    // a1/a2 are kernel inputs (no dependency on prep): load before GDS
    if (t < 128) sA1[t] = a1[h * DD + t];
    else sA2[t - 128] = a2[h * DD + (t - 128)];

    cudaGridDependencySynchronize();      // wait prep (g_featb / g_Wb)

    float acc[16][4];
    #pragma unroll
    for (int i = 0; i < 16; i++)
        #pragma unroll
        for (int j = 0; j < 4; j++) acc[i][j] = 0.0f;

    // issue chunk 0
    {
        #pragma unroll
        for (int r = 0; r < 4; r++) {
            int li = r * 256 + t;
            int row = li >> 3, q = li & 7;
            CP_ASYNC16(sA0 + row * 144 + q * 16,
                       g_featb + (size_t)(rowbase + row) * FF + q * 8);
        }
        #pragma unroll
        for (int r = 0; r < 4; r++) {
            int li = r * 256 + t;
            int row = li >> 4, q = li & 15;
            CP_ASYNC16(sB0 + row * 272 + q * 16,
                       g_Wb + ((size_t)h * FF + row) * DD + q * 8);
        }
    }
    CP_COMMIT;

    for (int c = 0; c < FF / 64; c++) {
        int kc = c * 64;
        if (c + 1 < FF / 64) {
            int nb_ = (c + 1) & 1;
            #pragma unroll
            for (int r = 0; r < 4; r++) {
                int li = r * 256 + t;
                int row = li >> 3, q = li & 7;
                CP_ASYNC16(sA0 + nb_ * PSA_BUF + row * 144 + q * 16,
                           g_featb + (size_t)(rowbase + row) * FF + kc + 64 + q * 8);
            }
            #pragma unroll
            for (int r = 0; r < 4; r++) {
                int li = r * 256 + t;
                int row = li >> 4, q = li & 15;
                CP_ASYNC16(sB0 + nb_ * PSB_BUF + row * 272 + q * 16,
                           g_Wb + ((size_t)h * FF + kc + 64 + row) * DD + q * 8);
            }
        }
        CP_COMMIT;
        if (c + 1 < FF / 64) { CP_WAIT1; } else { CP_WAIT0; }
        __syncthreads();

        int buf = c & 1;
        unsigned aBase = sA0 + buf * PSA_BUF;
        unsigned bBase = sB0 + buf * PSB_BUF;
        #pragma unroll
        for (int kk = 0; kk < 64; kk += 16) {
            unsigned a0, a1r, a2r, a3;
            ldsm_x4(aBase + (m0 + lr) * 144 + (kk + lc) * 2, a0, a1r, a2r, a3);
            #pragma unroll
            for (int nb = 0; nb < 8; nb++) {
                unsigned b0, b1, b2, b3;
                ldsm_x4_t(bBase + (kk + lr) * 272 + (nb * 16 + lc) * 2, b0, b1, b2, b3);
                mma_bf16(acc[2 * nb], a0, a1r, a2r, a3, b0, b1);
                mma_bf16(acc[2 * nb + 1], a0, a1r, a2r, a3, b2, b3);
            }
        }
        __syncthreads();
    }

    int row_lo = rowbase + m0 + g;
    int row_hi = row_lo + 8;

    // write Wh (bf16, row-major [h][j][d])
    __nv_bfloat16* outlo = g_Whb + ((size_t)h * NN + row_lo) * DD;
    __nv_bfloat16* outhi = g_Whb + ((size_t)h * NN + row_hi) * DD;
    #pragma unroll
    for (int i = 0; i < 16; i++) {
        int col = i * 8 + 2 * tid4;
        *(unsigned*)(outlo + col) = pack_bf16x2(acc[i][0], acc[i][1]);
        *(unsigned*)(outhi + col) = pack_bf16x2(acc[i][2], acc[i][3]);
    }

    // fused s1/s2 dot products from fp32 accumulators
    float d1lo = 0, d2lo = 0, d1hi = 0, d2hi = 0;
    #pragma unroll
    for (int i = 0; i < 16; i++) {
        int col = i * 8 + 2 * tid4;
        float v1a = sA1[col], v1b = sA1[col + 1];
        float v2a = sA2[col], v2b = sA2[col + 1];
        d1lo += acc[i][0] * v1a + acc[i][1] * v1b;
        d1hi += acc[i][2] * v1a + acc[i][3] * v1b;
        d2lo += acc[i][0] * v2a + acc[i][1] * v2b;
        d2hi += acc[i][2] * v2a + acc[i][3] * v2b;
    }
    #pragma unroll
    for (int o = 1; o <= 2; o <<= 1) {
        d1lo += __shfl_xor_sync(0xffffffffu, d1lo, o);
        d1hi += __shfl_xor_sync(0xffffffffu, d1hi, o);
        d2lo += __shfl_xor_sync(0xffffffffu, d2lo, o);
        d2hi += __shfl_xor_sync(0xffffffffu, d2hi, o);
    }
    if (tid4 == 0) {
        int ilo = h * NN + row_lo, ihi = h * NN + row_hi;
        g_ratio[ilo] = __expf(-0.8f * d1lo); g_ratio[ihi] = __expf(-0.8f * d1hi);
        g_e2p[ilo] = __expf(d2lo);           g_e2p[ihi] = __expf(d2hi);
        g_e2n[ilo] = __expf(0.2f * d2lo);    g_e2n[ihi] = __expf(0.2f * d2hi);
    }
}

// ---------------- kernel 4: fused masked-softmax aggregation; PDL consumer ----------------
#define OFF_P    0
#define OFF_B    16384
#define OFF_E2P  49152
#define OFF_E2N  65536
#define ATTN_SMEM_BYTES (81920 + 1024)

__global__ void __launch_bounds__(256, 2) attn_kernel() {
    extern __shared__ char smraw[];
    unsigned sb = (smem_u32(smraw) + 1023u) & ~1023u;
    unsigned sP = sb + OFF_P;
    unsigned sBb = sb + OFF_B;                 // + buf*16384 + half*8192
    unsigned sE2P = sb + OFF_E2P, sE2N = sb + OFF_E2N;

    int t = threadIdx.x;
    int w = t >> 5, lane = t & 31;
    int g = lane >> 2, tid4 = lane & 3;
    int mw = w & 3, nw = w >> 2;
    int m0 = mw * 32;
    int n0 = nw * 64;
    int lr = (lane & 7) + ((lane & 8) ? 8 : 0);
    int lc = (lane & 16) ? 8 : 0;
    int h = blockIdx.y;
    int rowbase = blockIdx.x * 128;

    // score-gen mapping (index math only; no dependent loads yet)
    int prow = t >> 1;
    int phalf = t & 1;
    int srow = rowbase + prow;

    cudaGridDependencySynchronize();      // wait proj (Whb / ratio / e2 tables)

    float ratio = g_ratio[h * NN + srow];

    // stage e2p/e2n (whole head, 16 KB each) + B tile 0, one cp.async group
    #pragma unroll
    for (int r = 0; r < 4; r++) {
        CP_ASYNC16(sE2P + (t + r * 256) * 16, g_e2p + (size_t)h * NN + (t + r * 256) * 4);
        CP_ASYNC16(sE2N + (t + r * 256) * 16, g_e2n + (size_t)h * NN + (t + r * 256) * 4);
    }
    {
        const __nv_bfloat16* src = g_Whb + (size_t)h * NN * DD;
        #pragma unroll
        for (int r = 0; r < 4; r++) {
            int li = r * 256 + t;
            int row = li >> 4, q = li & 15;
            CP_ASYNC16(sBb + (q >> 3) * 8192 + SWZ(row * 128 + (q & 7) * 16),
                       src + row * DD + q * 8);
        }
    }
    CP_COMMIT;
    CP_WAIT0;
    __syncthreads();

    float acc[16][4];
    #pragma unroll
    for (int i = 0; i < 16; i++)
        #pragma unroll
        for (int j = 0; j < 4; j++) acc[i][j] = 0.0f;
    float zA[4] = {0, 0, 0, 0}, zB[4] = {0, 0, 0, 0};
    const unsigned ONES = 0x3f803f80u;          // bf16 (1.0, 1.0)

    for (int i = 0; i < NCHUNK; i++) {
        int kc = i * KC;
        // prefetch B(i+1)
        if (i + 1 < NCHUNK) {
            const __nv_bfloat16* src = g_Whb + ((size_t)h * NN + kc + KC) * DD;
            unsigned dstb = sBb + ((i + 1) & 1) * 16384;
            #pragma unroll
            for (int r = 0; r < 4; r++) {
                int li = r * 256 + t;
                int row = li >> 4, q = li & 15;
                CP_ASYNC16(dstb + (q >> 3) * 8192 + SWZ(row * 128 + (q & 7) * 16),
                           src + row * DD + q * 8);
            }
        }
        CP_COMMIT;

        // score-gen: 32 q values for (srow, cols kc+phalf*32 .. +31) -> swizzled sP
        unsigned bw = g_adjbits[(size_t)srow * (NN / 32) + i * 2 + phalf];
        #pragma unroll
        for (int gi = 0; gi < 4; gi++) {
            int c = phalf * 32 + gi * 8;
            float4 ep0, ep1, en0, en1;
            lds128f(ep0, sE2P + (kc + c) * 4);
            lds128f(ep1, sE2P + (kc + c) * 4 + 16);
            lds128f(en0, sE2N + (kc + c) * 4);
            lds128f(en1, sE2N + (kc + c) * 4 + 16);
            unsigned mb = bw >> (gi * 8);
            float q0 = (mb & 1u)   ? fmaxf(ep0.x, ratio * en0.x) : 0.0f;
            float q1 = (mb & 2u)   ? fmaxf(ep0.y, ratio * en0.y) : 0.0f;
            float q2 = (mb & 4u)   ? fmaxf(ep0.z, ratio * en0.z) : 0.0f;
            float q3 = (mb & 8u)   ? fmaxf(ep0.w, ratio * en0.w) : 0.0f;
            float q4 = (mb & 16u)  ? fmaxf(ep1.x, ratio * en1.x) : 0.0f;
            float q5 = (mb & 32u)  ? fmaxf(ep1.y, ratio * en1.y) : 0.0f;
            float q6 = (mb & 64u)  ? fmaxf(ep1.z, ratio * en1.z) : 0.0f;
            float q7 = (mb & 128u) ? fmaxf(ep1.w, ratio * en1.w) : 0.0f;
            sts128(sP + SWZ(prow * 128 + c * 2),
                   pack_bf16x2(q0, q1), pack_bf16x2(q2, q3),
                   pack_bf16x2(q4, q5), pack_bf16x2(q6, q7));
        }

        CP_WAIT1;                 // B(i) resident; B(i+1) may be in flight
        __syncthreads();          // P(i) visible to all warps

        unsigned bhalf = sBb + (i & 1) * 16384 + nw * 8192;
        #pragma unroll
        for (int kk = 0; kk < 4; kk++) {
            unsigned A00, A01, A02, A03, A10, A11, A12, A13;
            ldsm_x4(sP + SWZ((m0 + lr) * 128 + (kk * 16 + lc) * 2), A00, A01, A02, A03);
            ldsm_x4(sP + SWZ((m0 + 16 + lr) * 128 + (kk * 16 + lc) * 2), A10, A11, A12, A13);
            #pragma unroll
            for (int nb4 = 0; nb4 < 4; nb4++) {
                unsigned b0, b1, b2, b3;
                ldsm_x4_t(bhalf + SWZ((kk * 16 + lr) * 128 + (nb4 * 16 + lc) * 2),
                          b0, b1, b2, b3);
                mma_bf16(acc[2 * nb4],     A00, A01, A02, A03, b0, b1);
                mma_bf16(acc[2 * nb4 + 1], A00, A01, A02, A03, b2, b3);
                mma_bf16(acc[8 + 2 * nb4],     A10, A11, A12, A13, b0, b1);
                mma_bf16(acc[8 + 2 * nb4 + 1], A10, A11, A12, A13, b2, b3);
            }
            mma_bf16(zA, A00, A01, A02, A03, ONES, ONES);   // Z rows m0+g, m0+g+8
            mma_bf16(zB, A10, A11, A12, A13, ONES, ONES);   // Z rows +16, +24
        }
        __syncthreads();          // P(i) consumed; safe to overwrite next iter
    }

    // normalize + ELU + per-head store
    int r0 = rowbase + m0 + g;
    float i0 = 1.0f / zA[0];
    float i1 = 1.0f / zA[2];
    float i2 = 1.0f / zB[0];
    float i3 = 1.0f / zB[2];
    float* o0 = g_haccum + ((size_t)h * NN + r0) * DD;
    float* o1 = o0 + 8 * DD;
    float* o2 = o0 + 16 * DD;
    float* o3 = o0 + 24 * DD;
    #pragma unroll
    for (int nb = 0; nb < 8; nb++) {
        int col = n0 + nb * 8 + 2 * tid4;
        float2 v0 = make_float2(elu1(acc[nb][0] * i0), elu1(acc[nb][1] * i0));
        float2 v1 = make_float2(elu1(acc[nb][2] * i1), elu1(acc[nb][3] * i1));
        float2 v2 = make_float2(elu1(acc[8 + nb][0] * i2), elu1(acc[8 + nb][1] * i2));
        float2 v3 = make_float2(elu1(acc[8 + nb][2] * i3), elu1(acc[8 + nb][3] * i3));
        *(float2*)(o0 + col) = v0;
        *(float2*)(o1 + col) = v1;
        *(float2*)(o2 + col) = v2;
        *(float2*)(o3 + col) = v3;
    }
}

// ---------------- kernel 5: head-sum -> /H -> log_softmax -> mean; PDL consumer ----------------
__global__ void final_kernel(float* __restrict__ out) {
    int warp = threadIdx.x >> 5;
    int lane = threadIdx.x & 31;
    int row = blockIdx.x * 8 + warp;               // 512 blocks -> 4096 rows
    cudaGridDependencySynchronize();               // wait attn (g_haccum)
    float x0 = 0, x1 = 0, x2 = 0, x3 = 0;
    #pragma unroll
    for (int hh = 0; hh < HH; hh++) {
        float4 v = *(const float4*)(g_haccum + ((size_t)hh * NN + row) * DD + lane * 4);
        x0 += v.x; x1 += v.y; x2 += v.z; x3 += v.w;
    }
    x0 *= 0.125f; x1 *= 0.125f; x2 *= 0.125f; x3 *= 0.125f;
    float mx = fmaxf(fmaxf(x0, x1), fmaxf(x2, x3));
    #pragma unroll
    for (int o = 16; o; o >>= 1) mx = fmaxf(mx, __shfl_xor_sync(0xffffffffu, mx, o));
    float se = __expf(x0 - mx) + __expf(x1 - mx) + __expf(x2 - mx) + __expf(x3 - mx);
    float sx = x0 + x1 + x2 + x3;
    #pragma unroll
    for (int o = 16; o; o >>= 1) {
        se += __shfl_xor_sync(0xffffffffu, se, o);
        sx += __shfl_xor_sync(0xffffffffu, sx, o);
    }
    if (lane == 0) out[row] = sx * (1.0f / 128.0f) - mx - logf(se);
}

// ---------------- launch: fork-join pack + PDL chain prep->proj->attn->final ----------------
extern "C" void kernel_launch(void* const* d_in, const int* in_sizes, int n_in,
                              void* d_out, int out_size) {
    const float* feature = (const float*)d_in[0];
    const int* adj = (const int*)d_in[1];
    const float* W = (const float*)d_in[2];
    const float* a1 = (const float*)d_in[3];
    const float* a2 = (const float*)d_in[4];
    float* out = (float*)d_out;

    static cudaStream_t s_pack = nullptr;
    static cudaEvent_t ev_fork = nullptr, ev_join = nullptr;
    if (!s_pack) {   // created on the (uncaptured) correctness call; alloc-safe pattern
        cudaStreamCreateWithFlags(&s_pack, cudaStreamNonBlocking);
        cudaEventCreateWithFlags(&ev_fork, cudaEventDisableTiming);
        cudaEventCreateWithFlags(&ev_join, cudaEventDisableTiming);
        cudaFuncSetAttribute(proj_kernel, cudaFuncAttributeMaxDynamicSharedMemorySize,
                             PROJ_SMEM_BYTES);
        cudaFuncSetAttribute(attn_kernel, cudaFuncAttributeMaxDynamicSharedMemorySize,
                             ATTN_SMEM_BYTES);
    }

    // fork: pack_adj (HBM-bound, independent) runs concurrently with prep+proj
    cudaEventRecord(ev_fork, 0);
    cudaStreamWaitEvent(s_pack, ev_fork, 0);
    pack_adj_kernel<<<65536, 256, 0, s_pack>>>(adj);
    cudaEventRecord(ev_join, s_pack);

    prep_kernel<<<2048, 256>>>(feature, W);

    // PDL attribute shared by the chained launches
    cudaLaunchAttribute pdl[1];
    pdl[0].id = cudaLaunchAttributeProgrammaticStreamSerialization;
    pdl[0].val.programmaticStreamSerializationAllowed = 1;

    {   // proj: overlaps prep tail (GDS inside)
        cudaLaunchConfig_t cfg = {};
        cfg.gridDim = dim3(32, 8, 1);
        cfg.blockDim = dim3(256, 1, 1);
        cfg.dynamicSmemBytes = PROJ_SMEM_BYTES;
        cfg.stream = 0;
        cfg.attrs = pdl;
        cfg.numAttrs = 1;
        cudaLaunchKernelEx(&cfg, proj_kernel, a1, a2);
    }

    // join: attn needs g_adjbits (default full-completion edge)
    cudaStreamWaitEvent(0, ev_join, 0);

    {   // attn: overlaps proj tail (GDS inside)
        cudaLaunchConfig_t cfg = {};
        cfg.gridDim = dim3(32, 8, 1);
        cfg.blockDim = dim3(256, 1, 1);
        cfg.dynamicSmemBytes = ATTN_SMEM_BYTES;
        cfg.stream = 0;
        cfg.attrs = pdl;
        cfg.numAttrs = 1;
        cudaLaunchKernelEx(&cfg, attn_kernel);
    }

    {   // final: overlaps attn tail (GDS inside)
        cudaLaunchConfig_t cfg = {};
        cfg.gridDim = dim3(512, 1, 1);
        cfg.blockDim = dim3(256, 1, 1);
        cfg.dynamicSmemBytes = 0;
        cfg.stream = 0;
        cfg.attrs = pdl;
        cfg.numAttrs = 1;
        cudaLaunchKernelEx(&cfg, final_kernel, out);
    }
}